// round 1
// baseline (speedup 1.0000x reference)
#include <cuda_runtime.h>

// Problem constants
constexpr int Bc = 2;
constexpr int Sc = 2048;
constexpr int Hc = 16;
constexpr int Dc = 64;
constexpr int HID = 1024;
constexpr float SCALE = 0.03125f;  // 1/sqrt(1024)

// Scratch: [B,H,S,D] for q,k,v ; [B,S,H,D] (= [B,S,HID]) for attention output
__device__ float g_q[Bc * Hc * Sc * Dc];
__device__ float g_k[Bc * Hc * Sc * Dc];
__device__ float g_v[Bc * Hc * Sc * Dc];
__device__ float g_att[Bc * Sc * Hc * Dc];

// ---------------------------------------------------------------------------
// Kernel 1: fused QKV projection.
// In  : x viewed as [B*S*H, 64] contiguous rows; W [64,64] row-major (out,e); bias[64]
// Out : [B,H,S,D]
// grid (1024, 3) blocks of 256; each block: 64 rows x 64 cols, 4x4 per thread.
// ---------------------------------------------------------------------------
__global__ __launch_bounds__(256) void proj_kernel(
    const float* __restrict__ xq, const float* __restrict__ xk, const float* __restrict__ xv,
    const float* __restrict__ Wq, const float* __restrict__ bq,
    const float* __restrict__ Wk, const float* __restrict__ bk,
    const float* __restrict__ Wv, const float* __restrict__ bv)
{
    __shared__ float Ws[64][65];
    __shared__ float Xs[64][65];

    const int which = blockIdx.y;
    const float* X    = (which == 0) ? xq : (which == 1) ? xk : xv;
    const float* W    = (which == 0) ? Wq : (which == 1) ? Wk : Wv;
    const float* bias = (which == 0) ? bq : (which == 1) ? bk : bv;
    float* out        = (which == 0) ? g_q : (which == 1) ? g_k : g_v;

    const int tid = threadIdx.x;
    const long r0 = (long)blockIdx.x * 64;

    for (int i = tid; i < 4096; i += 256) {
        Ws[i >> 6][i & 63] = W[i];
        Xs[i >> 6][i & 63] = X[r0 * 64 + i];
    }
    __syncthreads();

    const int tq = tid >> 4;   // row group 0..15
    const int tc = tid & 15;   // col group 0..15
    float acc[4][4] = {};

    #pragma unroll 8
    for (int e = 0; e < 64; e++) {
        float xr[4], wc[4];
        #pragma unroll
        for (int i = 0; i < 4; i++) xr[i] = Xs[tq * 4 + i][e];
        #pragma unroll
        for (int j = 0; j < 4; j++) wc[j] = Ws[tc * 4 + j][e];
        #pragma unroll
        for (int i = 0; i < 4; i++)
            #pragma unroll
            for (int j = 0; j < 4; j++)
                acc[i][j] += xr[i] * wc[j];
    }

    #pragma unroll
    for (int i = 0; i < 4; i++) {
        const int r = (int)r0 + tq * 4 + i;       // r = (b*S + s)*H + h
        const int b = r >> 15;                    // / (S*H) = / 32768
        const int s = (r >> 4) & 2047;
        const int h = r & 15;
        float* op = out + (((long)(b * Hc + h) * Sc + s) * Dc);
        #pragma unroll
        for (int j = 0; j < 4; j++) {
            const int d = tc * 4 + j;
            op[d] = acc[i][j] + bias[d];
        }
    }
}

// ---------------------------------------------------------------------------
// Kernel 2: flash attention per (b,h,q-tile of 64). 1024 blocks of 256.
// Online softmax, 4x4 register micro-tiles, P staged through the mask smem
// region (same-thread element reuse -> only __syncwarp needed for P exchange).
// ---------------------------------------------------------------------------
__global__ __launch_bounds__(256) void attn_kernel(const int* __restrict__ mask)
{
    extern __shared__ float sm[];
    float (*Qs)[65] = (float(*)[65])sm;
    float (*Ks)[65] = (float(*)[65])(sm + 64 * 65);
    float (*Vs)[65] = (float(*)[65])(sm + 2 * 64 * 65);
    float (*Ps)[65] = (float(*)[65])(sm + 3 * 64 * 65);
    int* Ms = (int*)(sm + 3 * 64 * 65);  // unioned with Ps

    const int tid = threadIdx.x;
    const int bh = blockIdx.x >> 5;      // 0..31  (b*16+h)
    const int qt = blockIdx.x & 31;      // q tile 0..31
    const int b = bh >> 4;

    const float* Qg = g_q + (long)bh * Sc * Dc + qt * 64 * Dc;
    const float* Kg = g_k + (long)bh * Sc * Dc;
    const float* Vg = g_v + (long)bh * Sc * Dc;
    const int*   Mg = mask + (long)b * Sc * Sc + (long)(qt * 64) * Sc;

    for (int i = tid; i < 4096; i += 256) Qs[i >> 6][i & 63] = Qg[i];

    const int tq = tid >> 4;   // query group 0..15 (4 rows)
    const int tk = tid & 15;   // key/dim group 0..15 (4 cols)

    float m[4], l[4], o[4][4];
    #pragma unroll
    for (int i = 0; i < 4; i++) {
        m[i] = -1e30f; l[i] = 0.0f;
        #pragma unroll
        for (int j = 0; j < 4; j++) o[i][j] = 0.0f;
    }

    for (int kt = 0; kt < 32; kt++) {
        __syncthreads();  // previous-iter readers done before overwrite (also covers Qs at kt=0)
        for (int i = tid; i < 4096; i += 256) {
            const int row = i >> 6, col = i & 63;
            Ks[row][col] = Kg[kt * 4096 + i];
            Vs[row][col] = Vg[kt * 4096 + i];
            Ms[row * 65 + col] = Mg[(long)row * Sc + kt * 64 + col];
        }
        __syncthreads();

        // scores: sc[i][j] = Q[tq*4+i] . K[tk*4+j]
        float sc[4][4] = {};
        #pragma unroll 8
        for (int e = 0; e < 64; e++) {
            float qv[4], kv[4];
            #pragma unroll
            for (int i = 0; i < 4; i++) qv[i] = Qs[tq * 4 + i][e];
            #pragma unroll
            for (int j = 0; j < 4; j++) kv[j] = Ks[tk * 4 + j][e];
            #pragma unroll
            for (int i = 0; i < 4; i++)
                #pragma unroll
                for (int j = 0; j < 4; j++)
                    sc[i][j] += qv[i] * kv[j];
        }

        // mask + scale (mask==0 -> -1e20 BEFORE the 1/32 scale, matching ref)
        #pragma unroll
        for (int i = 0; i < 4; i++)
            #pragma unroll
            for (int j = 0; j < 4; j++) {
                const int mv = Ms[(tq * 4 + i) * 65 + (tk * 4 + j)];
                sc[i][j] = (mv != 0 ? sc[i][j] : -1e20f) * SCALE;
            }

        // online softmax: row max / sum across the 16 lanes sharing a q group
        float mnew[4], corr[4], rs[4];
        #pragma unroll
        for (int i = 0; i < 4; i++) {
            float rm = fmaxf(fmaxf(sc[i][0], sc[i][1]), fmaxf(sc[i][2], sc[i][3]));
            rm = fmaxf(rm, __shfl_xor_sync(0xffffffffu, rm, 1));
            rm = fmaxf(rm, __shfl_xor_sync(0xffffffffu, rm, 2));
            rm = fmaxf(rm, __shfl_xor_sync(0xffffffffu, rm, 4));
            rm = fmaxf(rm, __shfl_xor_sync(0xffffffffu, rm, 8));
            mnew[i] = fmaxf(m[i], rm);
            corr[i] = __expf(m[i] - mnew[i]);
            m[i] = mnew[i];
        }

        #pragma unroll
        for (int i = 0; i < 4; i++) {
            rs[i] = 0.0f;
            #pragma unroll
            for (int j = 0; j < 4; j++) {
                const float p = __expf(sc[i][j] - mnew[i]);
                Ps[tq * 4 + i][tk * 4 + j] = p;   // same slot this thread read Ms from
                rs[i] += p;
            }
        }
        #pragma unroll
        for (int i = 0; i < 4; i++) {
            rs[i] += __shfl_xor_sync(0xffffffffu, rs[i], 1);
            rs[i] += __shfl_xor_sync(0xffffffffu, rs[i], 2);
            rs[i] += __shfl_xor_sync(0xffffffffu, rs[i], 4);
            rs[i] += __shfl_xor_sync(0xffffffffu, rs[i], 8);
            l[i] = l[i] * corr[i] + rs[i];
            #pragma unroll
            for (int j = 0; j < 4; j++) o[i][j] *= corr[i];
        }
        __syncwarp();  // P rows exchanged only within the owning half-warp

        // O += P @ V  (thread: rows tq*4+i, dims tk*4+j)
        #pragma unroll 8
        for (int jj = 0; jj < 64; jj++) {
            float pi[4], vj[4];
            #pragma unroll
            for (int i = 0; i < 4; i++) pi[i] = Ps[tq * 4 + i][jj];
            #pragma unroll
            for (int j = 0; j < 4; j++) vj[j] = Vs[jj][tk * 4 + j];
            #pragma unroll
            for (int i = 0; i < 4; i++)
                #pragma unroll
                for (int j = 0; j < 4; j++)
                    o[i][j] += pi[i] * vj[j];
        }
    }

    // normalize and write [B,S,H,D]
    const int h = bh & 15;
    #pragma unroll
    for (int i = 0; i < 4; i++) {
        const float inv = 1.0f / l[i];
        const int q = qt * 64 + tq * 4 + i;
        float* op = g_att + (((long)(b * Sc + q) * Hc + h) * Dc);
        #pragma unroll
        for (int j = 0; j < 4; j++)
            op[tk * 4 + j] = o[i][j] * inv;
    }
}

// ---------------------------------------------------------------------------
// Kernel 3: out = att[4096,1024] @ Wo^T + bo.  grid (64,16), 256 threads, 4x4.
// ---------------------------------------------------------------------------
__global__ __launch_bounds__(256) void outproj_kernel(
    const float* __restrict__ Wo, const float* __restrict__ bo, float* __restrict__ out)
{
    __shared__ float As[64][65];
    __shared__ float Bs[64][65];

    const int tid = threadIdx.x;
    const int r0 = blockIdx.x * 64;
    const int c0 = blockIdx.y * 64;
    const int tq = tid >> 4, tc = tid & 15;
    float acc[4][4] = {};

    for (int kt = 0; kt < 16; kt++) {
        __syncthreads();
        for (int i = tid; i < 4096; i += 256) {
            const int row = i >> 6, col = i & 63;
            As[row][col] = g_att[(long)(r0 + row) * HID + kt * 64 + col];
            Bs[row][col] = Wo[(long)(c0 + row) * HID + kt * 64 + col];
        }
        __syncthreads();

        #pragma unroll 8
        for (int e = 0; e < 64; e++) {
            float a[4], w[4];
            #pragma unroll
            for (int i = 0; i < 4; i++) a[i] = As[tq * 4 + i][e];
            #pragma unroll
            for (int j = 0; j < 4; j++) w[j] = Bs[tc * 4 + j][e];
            #pragma unroll
            for (int i = 0; i < 4; i++)
                #pragma unroll
                for (int j = 0; j < 4; j++)
                    acc[i][j] += a[i] * w[j];
        }
    }

    #pragma unroll
    for (int i = 0; i < 4; i++)
        #pragma unroll
        for (int j = 0; j < 4; j++)
            out[(long)(r0 + tq * 4 + i) * HID + c0 + tc * 4 + j] =
                acc[i][j] + bo[c0 + tc * 4 + j];
}

// ---------------------------------------------------------------------------
extern "C" void kernel_launch(void* const* d_in, const int* in_sizes, int n_in,
                              void* d_out, int out_size)
{
    const float* q    = (const float*)d_in[0];
    const float* k    = (const float*)d_in[1];
    const float* v    = (const float*)d_in[2];
    const int*   mask = (const int*)  d_in[3];
    const float* Wq   = (const float*)d_in[4];
    const float* bq   = (const float*)d_in[5];
    const float* Wk   = (const float*)d_in[6];
    const float* bk   = (const float*)d_in[7];
    const float* Wv   = (const float*)d_in[8];
    const float* bv   = (const float*)d_in[9];
    const float* Wo   = (const float*)d_in[10];
    const float* bo   = (const float*)d_in[11];
    float* out = (float*)d_out;

    const int smem = 4 * 64 * 65 * (int)sizeof(float);  // 66560 B
    cudaFuncSetAttribute(attn_kernel, cudaFuncAttributeMaxDynamicSharedMemorySize, smem);

    proj_kernel<<<dim3(1024, 3), 256>>>(q, k, v, Wq, bq, Wk, bk, Wv, bv);
    attn_kernel<<<1024, 256, smem>>>(mask);
    outproj_kernel<<<dim3(64, 16), 256>>>(Wo, bo, out);
}

// round 3
// speedup vs baseline: 3.9912x; 3.9912x over previous
#include <cuda_runtime.h>
#include <cuda_fp16.h>
#include <cstdint>

// ---------------- problem constants ----------------
constexpr int Bc = 2;
constexpr int Sc = 2048;
constexpr int Hc = 16;
constexpr int Dc = 64;
constexpr int HID = 1024;
constexpr float CE = 0.03125f * 1.44269504088896340736f;  // (1/sqrt(1024)) * log2(e)

// ---------------- device scratch ----------------
__device__ __half   g_q[Bc * Hc * Sc * Dc];        // [B,H,S,D] fp16
__device__ __half   g_k[Bc * Hc * Sc * Dc];        // [B,H,S,D] fp16
__device__ __half   g_v[Bc * Hc * Sc * Dc];        // [B,H,S,D] fp16
__device__ float    g_att[Bc * Sc * HID];          // [B,S,HID] fp32
__device__ uint32_t g_maskp[Bc * Sc * (Sc / 32)];  // bit-packed mask

// ---------------- helpers ----------------
__device__ __forceinline__ uint32_t smem_u32(const void* p) {
    uint32_t a;
    asm("{ .reg .u64 t; cvta.to.shared.u64 t, %1; cvt.u32.u64 %0, t; }" : "=r"(a) : "l"(p));
    return a;
}
__device__ __forceinline__ uint32_t SW(uint32_t x) { return x ^ ((x >> 3) & 0x70); }

__device__ __forceinline__ void ldsm4(uint32_t* r, uint32_t a) {
    asm volatile("ldmatrix.sync.aligned.m8n8.x4.shared.b16 {%0,%1,%2,%3}, [%4];"
                 : "=r"(r[0]), "=r"(r[1]), "=r"(r[2]), "=r"(r[3]) : "r"(a));
}
__device__ __forceinline__ void ldsm4t(uint32_t* r, uint32_t a) {
    asm volatile("ldmatrix.sync.aligned.m8n8.x4.trans.shared.b16 {%0,%1,%2,%3}, [%4];"
                 : "=r"(r[0]), "=r"(r[1]), "=r"(r[2]), "=r"(r[3]) : "r"(a));
}
__device__ __forceinline__ void mma16816(float* c, const uint32_t* a, const uint32_t* b) {
    asm volatile("mma.sync.aligned.m16n8k16.row.col.f32.f16.f16.f32 "
                 "{%0,%1,%2,%3}, {%4,%5,%6,%7}, {%8,%9}, {%0,%1,%2,%3};"
                 : "+f"(c[0]), "+f"(c[1]), "+f"(c[2]), "+f"(c[3])
                 : "r"(a[0]), "r"(a[1]), "r"(a[2]), "r"(a[3]), "r"(b[0]), "r"(b[1]));
}
__device__ __forceinline__ void cp16(uint32_t d, const void* s) {
    asm volatile("cp.async.cg.shared.global [%0], [%1], 16;" :: "r"(d), "l"(s) : "memory");
}
__device__ __forceinline__ void cp8(uint32_t d, const void* s) {
    asm volatile("cp.async.ca.shared.global [%0], [%1], 8;" :: "r"(d), "l"(s) : "memory");
}
__device__ __forceinline__ void cp_commit() {
    asm volatile("cp.async.commit_group;" ::: "memory");
}
template <int N> __device__ __forceinline__ void cp_wait() {
    asm volatile("cp.async.wait_group %0;" :: "n"(N) : "memory");
}
__device__ __forceinline__ float ex2(float x) {
    float r;
    asm("ex2.approx.ftz.f32 %0, %1;" : "=f"(r) : "f"(x));
    return r;
}
__device__ __forceinline__ uint32_t packh2(float a, float b) {
    __half2 h = __floats2half2_rn(a, b);   // a -> low half
    return *reinterpret_cast<uint32_t*>(&h);
}

// ---------------------------------------------------------------------------
// Kernel 0: bit-pack the mask
// ---------------------------------------------------------------------------
__global__ __launch_bounds__(256) void pack_mask_kernel(const int* __restrict__ mask) {
    long i = (long)blockIdx.x * 256 + threadIdx.x;
    int v = mask[i];
    uint32_t bal = __ballot_sync(0xffffffffu, v != 0);
    if ((threadIdx.x & 31) == 0) g_maskp[i >> 5] = bal;
}

// ---------------------------------------------------------------------------
// Kernel 1: fused QKV projection with mma.sync (fp16 in, fp32 accum)
// grid (512, 3), 256 threads; CTA computes 128 rows x 64 cols.
// Rows of X are (b,s,h) with d contiguous; each warp's 16 rows = 16 heads of one (b,s).
// ---------------------------------------------------------------------------
__global__ __launch_bounds__(256) void proj_kernel(
    const float* __restrict__ xq, const float* __restrict__ xk, const float* __restrict__ xv,
    const float* __restrict__ Wq, const float* __restrict__ bq,
    const float* __restrict__ Wk, const float* __restrict__ bk,
    const float* __restrict__ Wv, const float* __restrict__ bv)
{
    __shared__ __half Xs[128 * 64];
    __shared__ __half Ws[64 * 64];
    __shared__ float  bs[64];

    const int which = blockIdx.y;
    const float* X    = (which == 0) ? xq : (which == 1) ? xk : xv;
    const float* Wt   = (which == 0) ? Wq : (which == 1) ? Wk : Wv;
    const float* bias = (which == 0) ? bq : (which == 1) ? bk : bv;
    __half* outp      = (which == 0) ? g_q : (which == 1) ? g_k : g_v;

    const int tid = threadIdx.x, lane = tid & 31, w = tid >> 5;
    const long R0 = (long)blockIdx.x * 128;

    const uint32_t xb = smem_u32(Xs), wb = smem_u32(Ws);
    const float4* Xg = (const float4*)(X + R0 * 64);
    for (int i = tid; i < 2048; i += 256) {           // 128x64 floats
        float4 f = Xg[i];
        uint32_t off = SW((uint32_t)i * 8);           // row*128 + q*8 == i*8
        *(__half2*)((char*)Xs + off)     = __floats2half2_rn(f.x, f.y);
        *(__half2*)((char*)Xs + off + 4) = __floats2half2_rn(f.z, f.w);
    }
    const float4* Wg = (const float4*)Wt;
    for (int i = tid; i < 1024; i += 256) {           // 64x64 floats
        float4 f = Wg[i];
        uint32_t off = SW((uint32_t)i * 8);
        *(__half2*)((char*)Ws + off)     = __floats2half2_rn(f.x, f.y);
        *(__half2*)((char*)Ws + off + 4) = __floats2half2_rn(f.z, f.w);
    }
    if (tid < 64) bs[tid] = bias[tid];
    __syncthreads();

    const int lr = lane & 7, g = lane >> 3, tq = lane >> 2, tr = lane & 3;
    const int m0 = w * 16;

    uint32_t qa[16];
    #pragma unroll
    for (int kc = 0; kc < 4; kc++)
        ldsm4(qa + kc * 4, xb + SW((m0 + lr + (g & 1) * 8) * 128 + kc * 32 + (g >> 1) * 16));

    float c[8][4] = {};
    #pragma unroll
    for (int nt = 0; nt < 8; nt++) {
        uint32_t bk[8];
        ldsm4(bk,     wb + SW((nt * 8 + lr) * 128 + g * 16));
        ldsm4(bk + 4, wb + SW((nt * 8 + lr) * 128 + g * 16 + 64));
        #pragma unroll
        for (int kc = 0; kc < 4; kc++) mma16816(c[nt], qa + 4 * kc, bk + 2 * kc);
    }

    // epilogue: rows m0..m0+15 share (b,s); h = row index within the 16
    const long Rw = R0 + m0;
    const int b = (int)(Rw >> 15);
    const int s = (int)((Rw >> 4) & 2047);
    #pragma unroll
    for (int nt = 0; nt < 8; nt++) {
        const int col = nt * 8 + tr * 2;
        const float b0 = bs[col], b1 = bs[col + 1];
        const int hl = tq, hh = tq + 8;
        __half2* lo = (__half2*)(outp + (((long)(b * Hc + hl) * Sc + s) * Dc) + col);
        __half2* hi = (__half2*)(outp + (((long)(b * Hc + hh) * Sc + s) * Dc) + col);
        *lo = __floats2half2_rn(c[nt][0] + b0, c[nt][1] + b1);
        *hi = __floats2half2_rn(c[nt][2] + b0, c[nt][3] + b1);
    }
}

// ---------------------------------------------------------------------------
// Kernel 2: flash attention with mma.sync.
// grid 512 (bh*16 + qtile), 256 threads (8 warps x 16 q-rows), K/V tiles of 64,
// cp.async double buffering. Scores stay in registers (C-frag -> A-frag trick).
// smem: Q 16K | K 2x8K | V 2x8K | mask 2x1K  = 51200 B
// ---------------------------------------------------------------------------
constexpr int ATT_SMEM = 51200;

__global__ __launch_bounds__(256, 2) void attn_kernel()
{
    extern __shared__ char sm[];
    const uint32_t sb = smem_u32(sm);
    const int tid = threadIdx.x, lane = tid & 31, w = tid >> 5;
    const int bh = blockIdx.x >> 4, qt = blockIdx.x & 15;
    const int b = bh >> 4, h = bh & 15;

    const __half* Qg = g_q + ((long)bh * Sc + qt * 128) * Dc;
    const __half* Kg = g_k + (long)bh * Sc * Dc;
    const __half* Vg = g_v + (long)bh * Sc * Dc;
    const uint32_t* Mp = g_maskp + ((long)b * Sc + qt * 128) * (Sc / 32);

    // Q tile: 128 rows x 128B, contiguous in global
    for (int i = tid; i < 1024; i += 256)
        cp16(sb + (((uint32_t)i * 16) & ~1023u) + SW(((uint32_t)i * 16) & 1023u),
             (const char*)Qg + (long)i * 16);

    auto prefetch = [&](int kt) {
        const int bo = kt & 1;
        const uint32_t kb = sb + 16384 + bo * 8192;
        const uint32_t vb = sb + 32768 + bo * 8192;
        const char* kg = (const char*)(Kg + (long)kt * 64 * 64);
        const char* vg = (const char*)(Vg + (long)kt * 64 * 64);
        for (int i = tid; i < 512; i += 256) {
            uint32_t off = (((uint32_t)i * 16) & ~1023u) + SW(((uint32_t)i * 16) & 1023u);
            cp16(kb + off, kg + (long)i * 16);
            cp16(vb + off, vg + (long)i * 16);
        }
        const uint32_t mb = sb + 49152 + bo * 1024;
        if (tid < 128)
            cp8(mb + tid * 8, (const void*)(Mp + (long)tid * 64 + kt * 2));
    };

    prefetch(0);
    cp_commit();

    const int lr = lane & 7, g = lane >> 3, tq = lane >> 2, tr = lane & 3;
    const int m0 = w * 16;

    uint32_t qa[16];
    float o[8][4] = {};
    float l0 = 0.0f, l1 = 0.0f;

    for (int kt = 0; kt < 32; kt++) {
        if (kt < 31) { prefetch(kt + 1); cp_commit(); cp_wait<1>(); }
        else         { cp_wait<0>(); }
        __syncthreads();

        const uint32_t kb = sb + 16384 + (kt & 1) * 8192;
        const uint32_t vb = sb + 32768 + (kt & 1) * 8192;
        const uint32_t* mrow = (const uint32_t*)(sm + 49152 + (kt & 1) * 1024);

        if (kt == 0) {
            #pragma unroll
            for (int kc = 0; kc < 4; kc++)
                ldsm4(qa + kc * 4, sb + SW((m0 + lr + (g & 1) * 8) * 128 + kc * 32 + (g >> 1) * 16));
        }

        // scores = Q @ K^T (16 x 64 per warp)
        float c[8][4] = {};
        #pragma unroll
        for (int nt = 0; nt < 8; nt++) {
            uint32_t bk[8];
            ldsm4(bk,     kb + SW((nt * 8 + lr) * 128 + g * 16));
            ldsm4(bk + 4, kb + SW((nt * 8 + lr) * 128 + g * 16 + 64));
            #pragma unroll
            for (int kc = 0; kc < 4; kc++) mma16816(c[nt], qa + 4 * kc, bk + 2 * kc);
        }

        // mask + exp; pack P as fp16 A-fragments
        const uint32_t ml0 = mrow[(m0 + tq) * 2],     mh0 = mrow[(m0 + tq) * 2 + 1];
        const uint32_t ml1 = mrow[(m0 + tq + 8) * 2], mh1 = mrow[(m0 + tq + 8) * 2 + 1];
        uint32_t pa[16];
        #pragma unroll
        for (int nt = 0; nt < 8; nt++) {
            const int sh = ((nt & 3) << 3) + tr * 2;
            const uint32_t w0 = (nt < 4) ? ml0 : mh0;
            const uint32_t w1 = (nt < 4) ? ml1 : mh1;
            float p0 = ex2(((w0 >> sh) & 1u)       ? c[nt][0] * CE : -1e30f);
            float p1 = ex2(((w0 >> (sh + 1)) & 1u) ? c[nt][1] * CE : -1e30f);
            float p2 = ex2(((w1 >> sh) & 1u)       ? c[nt][2] * CE : -1e30f);
            float p3 = ex2(((w1 >> (sh + 1)) & 1u) ? c[nt][3] * CE : -1e30f);
            l0 += p0 + p1;
            l1 += p2 + p3;
            pa[nt * 2]     = packh2(p0, p1);
            pa[nt * 2 + 1] = packh2(p2, p3);
        }

        // O += P @ V  (V via ldmatrix.trans)
        #pragma unroll
        for (int nt = 0; nt < 8; nt++) {
            uint32_t bv[8];
            ldsm4t(bv,     vb + SW((g * 8 + lr) * 128 + nt * 16));
            ldsm4t(bv + 4, vb + SW((g * 8 + lr + 32) * 128 + nt * 16));
            #pragma unroll
            for (int kc = 0; kc < 4; kc++) mma16816(o[nt], pa + 4 * kc, bv + 2 * kc);
        }
        __syncthreads();
    }

    // row sums across quads, normalize, write [B,S,HID]
    l0 += __shfl_xor_sync(0xffffffffu, l0, 1);
    l0 += __shfl_xor_sync(0xffffffffu, l0, 2);
    l1 += __shfl_xor_sync(0xffffffffu, l1, 1);
    l1 += __shfl_xor_sync(0xffffffffu, l1, 2);
    const float inv0 = 1.0f / l0, inv1 = 1.0f / l1;

    const int rl = qt * 128 + m0 + tq;
    float* og = g_att + ((long)b * Sc + rl) * HID + h * 64;
    #pragma unroll
    for (int nt = 0; nt < 8; nt++) {
        const int col = nt * 8 + tr * 2;
        *(float2*)(og + col)            = make_float2(o[nt][0] * inv0, o[nt][1] * inv0);
        *(float2*)(og + 8 * HID + col)  = make_float2(o[nt][2] * inv1, o[nt][3] * inv1);
    }
}

// ---------------------------------------------------------------------------
// Kernel 3: out = att @ Wo^T + bo, fp16 hi/lo split (3 mma terms).
// grid (32, 8), 256 threads; CTA tile 128x128, K chunks of 64.
// ---------------------------------------------------------------------------
__global__ __launch_bounds__(256, 2) void outproj_kernel(
    const float* __restrict__ Wo, const float* __restrict__ bo, float* __restrict__ out)
{
    __shared__ __half Ah[128 * 64], Al[128 * 64], Bh[128 * 64], Bl[128 * 64];

    const int tid = threadIdx.x, lane = tid & 31, w = tid >> 5;
    const int r0 = blockIdx.x * 128, c0 = blockIdx.y * 128;
    const int lr = lane & 7, g = lane >> 3, tq = lane >> 2, tr = lane & 3;
    const int m0 = w * 16;

    const uint32_t ah = smem_u32(Ah), al = smem_u32(Al);
    const uint32_t bhs = smem_u32(Bh), bls = smem_u32(Bl);

    float c[16][4] = {};

    for (int kc16 = 0; kc16 < 16; kc16++) {
        __syncthreads();
        for (int i = tid; i < 2048; i += 256) {
            const int row = i >> 4, q = i & 15;
            const uint32_t off = SW((uint32_t)(row * 128 + q * 8));

            float4 fa = *(const float4*)(g_att + (long)(r0 + row) * HID + kc16 * 64 + q * 4);
            __half hx = __float2half_rn(fa.x), hy = __float2half_rn(fa.y);
            __half hz = __float2half_rn(fa.z), hw = __float2half_rn(fa.w);
            *(__half2*)((char*)Ah + off)     = __halves2half2(hx, hy);
            *(__half2*)((char*)Ah + off + 4) = __halves2half2(hz, hw);
            *(__half2*)((char*)Al + off)     = __floats2half2_rn(fa.x - __half2float(hx), fa.y - __half2float(hy));
            *(__half2*)((char*)Al + off + 4) = __floats2half2_rn(fa.z - __half2float(hz), fa.w - __half2float(hw));

            float4 fb = *(const float4*)(Wo + (long)(c0 + row) * HID + kc16 * 64 + q * 4);
            __half gx = __float2half_rn(fb.x), gy = __float2half_rn(fb.y);
            __half gz = __float2half_rn(fb.z), gw = __float2half_rn(fb.w);
            *(__half2*)((char*)Bh + off)     = __halves2half2(gx, gy);
            *(__half2*)((char*)Bh + off + 4) = __halves2half2(gz, gw);
            *(__half2*)((char*)Bl + off)     = __floats2half2_rn(fb.x - __half2float(gx), fb.y - __half2float(gy));
            *(__half2*)((char*)Bl + off + 4) = __floats2half2_rn(fb.z - __half2float(gz), fb.w - __half2float(gw));
        }
        __syncthreads();

        #pragma unroll
        for (int term = 0; term < 3; term++) {
            const uint32_t At = (term == 2) ? al : ah;
            const uint32_t Bt = (term == 1) ? bls : bhs;
            uint32_t aa[16];
            #pragma unroll
            for (int kc = 0; kc < 4; kc++)
                ldsm4(aa + kc * 4, At + SW((m0 + lr + (g & 1) * 8) * 128 + kc * 32 + (g >> 1) * 16));
            #pragma unroll
            for (int nt = 0; nt < 16; nt++) {
                uint32_t bb[8];
                ldsm4(bb,     Bt + SW((nt * 8 + lr) * 128 + g * 16));
                ldsm4(bb + 4, Bt + SW((nt * 8 + lr) * 128 + g * 16 + 64));
                #pragma unroll
                for (int kc = 0; kc < 4; kc++) mma16816(c[nt], aa + 4 * kc, bb + 2 * kc);
            }
        }
    }

    const int rl = r0 + m0 + tq;
    #pragma unroll
    for (int nt = 0; nt < 16; nt++) {
        const int col = c0 + nt * 8 + tr * 2;
        const float b0 = bo[col], b1 = bo[col + 1];
        *(float2*)(out + (long)rl * HID + col)       = make_float2(c[nt][0] + b0, c[nt][1] + b1);
        *(float2*)(out + (long)(rl + 8) * HID + col) = make_float2(c[nt][2] + b0, c[nt][3] + b1);
    }
}

// ---------------------------------------------------------------------------
extern "C" void kernel_launch(void* const* d_in, const int* in_sizes, int n_in,
                              void* d_out, int out_size)
{
    const float* q    = (const float*)d_in[0];
    const float* k    = (const float*)d_in[1];
    const float* v    = (const float*)d_in[2];
    const int*   mask = (const int*)  d_in[3];
    const float* Wq   = (const float*)d_in[4];
    const float* bq   = (const float*)d_in[5];
    const float* Wk   = (const float*)d_in[6];
    const float* bk   = (const float*)d_in[7];
    const float* Wv   = (const float*)d_in[8];
    const float* bv   = (const float*)d_in[9];
    const float* Wo   = (const float*)d_in[10];
    const float* bo   = (const float*)d_in[11];
    float* out = (float*)d_out;

    cudaFuncSetAttribute(attn_kernel, cudaFuncAttributeMaxDynamicSharedMemorySize, ATT_SMEM);

    pack_mask_kernel<<<Bc * Sc * Sc / 256, 256>>>(mask);
    proj_kernel<<<dim3(512, 3), 256>>>(q, k, v, Wq, bq, Wk, bk, Wv, bv);
    attn_kernel<<<512, 256, ATT_SMEM>>>();
    outproj_kernel<<<dim3(32, 8), 256>>>(Wo, bo, out);
}

// round 4
// speedup vs baseline: 6.6604x; 1.6688x over previous
#include <cuda_runtime.h>
#include <cuda_fp16.h>
#include <cstdint>

// ---------------- problem constants ----------------
constexpr int Bc = 2;
constexpr int Sc = 2048;
constexpr int Hc = 16;
constexpr int Dc = 64;
constexpr int HID = 1024;
constexpr float CE = 0.03125f * 1.44269504088896340736f;  // (1/sqrt(1024)) * log2(e)

// ---------------- device scratch ----------------
__device__ __half   g_q[Bc * Hc * Sc * Dc];        // [B,H,S,D] fp16
__device__ __half   g_k[Bc * Hc * Sc * Dc];        // [B,H,S,D] fp16
__device__ __half   g_v[Bc * Hc * Sc * Dc];        // [B,H,S,D] fp16
__device__ __half   g_att[Bc * Sc * HID];          // [B,S,HID] fp16
__device__ __half   g_wo[HID * HID];               // Wo fp16
__device__ uint32_t g_maskp[Bc * Sc * (Sc / 32)];  // bit-packed mask

// ---------------- helpers ----------------
__device__ __forceinline__ uint32_t smem_u32(const void* p) {
    uint32_t a;
    asm("{ .reg .u64 t; cvta.to.shared.u64 t, %1; cvt.u32.u64 %0, t; }" : "=r"(a) : "l"(p));
    return a;
}
__device__ __forceinline__ uint32_t SW(uint32_t x) { return x ^ ((x >> 3) & 0x70); }

__device__ __forceinline__ void ldsm4(uint32_t* r, uint32_t a) {
    asm volatile("ldmatrix.sync.aligned.m8n8.x4.shared.b16 {%0,%1,%2,%3}, [%4];"
                 : "=r"(r[0]), "=r"(r[1]), "=r"(r[2]), "=r"(r[3]) : "r"(a));
}
__device__ __forceinline__ void ldsm4t(uint32_t* r, uint32_t a) {
    asm volatile("ldmatrix.sync.aligned.m8n8.x4.trans.shared.b16 {%0,%1,%2,%3}, [%4];"
                 : "=r"(r[0]), "=r"(r[1]), "=r"(r[2]), "=r"(r[3]) : "r"(a));
}
__device__ __forceinline__ void mma16816(float* c, const uint32_t* a, const uint32_t* b) {
    asm volatile("mma.sync.aligned.m16n8k16.row.col.f32.f16.f16.f32 "
                 "{%0,%1,%2,%3}, {%4,%5,%6,%7}, {%8,%9}, {%0,%1,%2,%3};"
                 : "+f"(c[0]), "+f"(c[1]), "+f"(c[2]), "+f"(c[3])
                 : "r"(a[0]), "r"(a[1]), "r"(a[2]), "r"(a[3]), "r"(b[0]), "r"(b[1]));
}
__device__ __forceinline__ void cp16(uint32_t d, const void* s) {
    asm volatile("cp.async.cg.shared.global [%0], [%1], 16;" :: "r"(d), "l"(s) : "memory");
}
__device__ __forceinline__ void cp8(uint32_t d, const void* s) {
    asm volatile("cp.async.ca.shared.global [%0], [%1], 8;" :: "r"(d), "l"(s) : "memory");
}
__device__ __forceinline__ void cp_commit() {
    asm volatile("cp.async.commit_group;" ::: "memory");
}
template <int N> __device__ __forceinline__ void cp_wait() {
    asm volatile("cp.async.wait_group %0;" :: "n"(N) : "memory");
}
__device__ __forceinline__ float ex2(float x) {
    float r;
    asm("ex2.approx.ftz.f32 %0, %1;" : "=f"(r) : "f"(x));
    return r;
}
__device__ __forceinline__ uint32_t packh2(float a, float b) {
    __half2 h = __floats2half2_rn(a, b);   // a -> low half
    return *reinterpret_cast<uint32_t*>(&h);
}

// ---------------------------------------------------------------------------
// Kernel 0a: bit-pack the mask
// ---------------------------------------------------------------------------
__global__ __launch_bounds__(256) void pack_mask_kernel(const int* __restrict__ mask) {
    long i = (long)blockIdx.x * 256 + threadIdx.x;
    int v = mask[i];
    uint32_t bal = __ballot_sync(0xffffffffu, v != 0);
    if ((threadIdx.x & 31) == 0) g_maskp[i >> 5] = bal;
}

// ---------------------------------------------------------------------------
// Kernel 0b: convert Wo to fp16 once
// ---------------------------------------------------------------------------
__global__ __launch_bounds__(256) void convert_wo_kernel(const float* __restrict__ Wo) {
    long i = (long)blockIdx.x * 256 + threadIdx.x;   // over 262144 float4s
    float4 f = ((const float4*)Wo)[i];
    ((__half2*)g_wo)[i * 2]     = __floats2half2_rn(f.x, f.y);
    ((__half2*)g_wo)[i * 2 + 1] = __floats2half2_rn(f.z, f.w);
}

// ---------------------------------------------------------------------------
// Kernel 1: fused QKV projection with mma.sync (fp16 in, fp32 accum)
// ---------------------------------------------------------------------------
__global__ __launch_bounds__(256) void proj_kernel(
    const float* __restrict__ xq, const float* __restrict__ xk, const float* __restrict__ xv,
    const float* __restrict__ Wq, const float* __restrict__ bq,
    const float* __restrict__ Wk, const float* __restrict__ bk,
    const float* __restrict__ Wv, const float* __restrict__ bv)
{
    __shared__ __half Xs[128 * 64];
    __shared__ __half Ws[64 * 64];
    __shared__ float  bs[64];

    const int which = blockIdx.y;
    const float* X    = (which == 0) ? xq : (which == 1) ? xk : xv;
    const float* Wt   = (which == 0) ? Wq : (which == 1) ? Wk : Wv;
    const float* bias = (which == 0) ? bq : (which == 1) ? bk : bv;
    __half* outp      = (which == 0) ? g_q : (which == 1) ? g_k : g_v;

    const int tid = threadIdx.x, lane = tid & 31, w = tid >> 5;
    const long R0 = (long)blockIdx.x * 128;

    const uint32_t xb = smem_u32(Xs), wb = smem_u32(Ws);
    const float4* Xg = (const float4*)(X + R0 * 64);
    for (int i = tid; i < 2048; i += 256) {
        float4 f = Xg[i];
        uint32_t off = SW((uint32_t)i * 8);
        *(__half2*)((char*)Xs + off)     = __floats2half2_rn(f.x, f.y);
        *(__half2*)((char*)Xs + off + 4) = __floats2half2_rn(f.z, f.w);
    }
    const float4* Wg = (const float4*)Wt;
    for (int i = tid; i < 1024; i += 256) {
        float4 f = Wg[i];
        uint32_t off = SW((uint32_t)i * 8);
        *(__half2*)((char*)Ws + off)     = __floats2half2_rn(f.x, f.y);
        *(__half2*)((char*)Ws + off + 4) = __floats2half2_rn(f.z, f.w);
    }
    if (tid < 64) bs[tid] = bias[tid];
    __syncthreads();

    const int lr = lane & 7, g = lane >> 3, tq = lane >> 2, tr = lane & 3;
    const int m0 = w * 16;

    uint32_t qa[16];
    #pragma unroll
    for (int kc = 0; kc < 4; kc++)
        ldsm4(qa + kc * 4, xb + SW((m0 + lr + (g & 1) * 8) * 128 + kc * 32 + (g >> 1) * 16));

    float c[8][4] = {};
    #pragma unroll
    for (int nt = 0; nt < 8; nt++) {
        uint32_t bk[8];
        ldsm4(bk,     wb + SW((nt * 8 + lr) * 128 + g * 16));
        ldsm4(bk + 4, wb + SW((nt * 8 + lr) * 128 + g * 16 + 64));
        #pragma unroll
        for (int kc = 0; kc < 4; kc++) mma16816(c[nt], qa + 4 * kc, bk + 2 * kc);
    }

    const long Rw = R0 + m0;
    const int b = (int)(Rw >> 15);
    const int s = (int)((Rw >> 4) & 2047);
    #pragma unroll
    for (int nt = 0; nt < 8; nt++) {
        const int col = nt * 8 + tr * 2;
        const float b0 = bs[col], b1 = bs[col + 1];
        const int hl = tq, hh = tq + 8;
        __half2* lo = (__half2*)(outp + (((long)(b * Hc + hl) * Sc + s) * Dc) + col);
        __half2* hi = (__half2*)(outp + (((long)(b * Hc + hh) * Sc + s) * Dc) + col);
        *lo = __floats2half2_rn(c[nt][0] + b0, c[nt][1] + b1);
        *hi = __floats2half2_rn(c[nt][2] + b0, c[nt][3] + b1);
    }
}

// ---------------------------------------------------------------------------
// Kernel 2: flash attention with mma.sync (unchanged mainloop; fp16 epilogue)
// ---------------------------------------------------------------------------
constexpr int ATT_SMEM = 51200;

__global__ __launch_bounds__(256, 2) void attn_kernel()
{
    extern __shared__ char sm[];
    const uint32_t sb = smem_u32(sm);
    const int tid = threadIdx.x, lane = tid & 31, w = tid >> 5;
    const int bh = blockIdx.x >> 4, qt = blockIdx.x & 15;
    const int b = bh >> 4, h = bh & 15;

    const __half* Qg = g_q + ((long)bh * Sc + qt * 128) * Dc;
    const __half* Kg = g_k + (long)bh * Sc * Dc;
    const __half* Vg = g_v + (long)bh * Sc * Dc;
    const uint32_t* Mp = g_maskp + ((long)b * Sc + qt * 128) * (Sc / 32);

    for (int i = tid; i < 1024; i += 256)
        cp16(sb + (((uint32_t)i * 16) & ~1023u) + SW(((uint32_t)i * 16) & 1023u),
             (const char*)Qg + (long)i * 16);

    auto prefetch = [&](int kt) {
        const int bo = kt & 1;
        const uint32_t kb = sb + 16384 + bo * 8192;
        const uint32_t vb = sb + 32768 + bo * 8192;
        const char* kg = (const char*)(Kg + (long)kt * 64 * 64);
        const char* vg = (const char*)(Vg + (long)kt * 64 * 64);
        for (int i = tid; i < 512; i += 256) {
            uint32_t off = (((uint32_t)i * 16) & ~1023u) + SW(((uint32_t)i * 16) & 1023u);
            cp16(kb + off, kg + (long)i * 16);
            cp16(vb + off, vg + (long)i * 16);
        }
        const uint32_t mb = sb + 49152 + bo * 1024;
        if (tid < 128)
            cp8(mb + tid * 8, (const void*)(Mp + (long)tid * 64 + kt * 2));
    };

    prefetch(0);
    cp_commit();

    const int lr = lane & 7, g = lane >> 3, tq = lane >> 2, tr = lane & 3;
    const int m0 = w * 16;

    uint32_t qa[16];
    float o[8][4] = {};
    float l0 = 0.0f, l1 = 0.0f;

    for (int kt = 0; kt < 32; kt++) {
        if (kt < 31) { prefetch(kt + 1); cp_commit(); cp_wait<1>(); }
        else         { cp_wait<0>(); }
        __syncthreads();

        const uint32_t kb = sb + 16384 + (kt & 1) * 8192;
        const uint32_t vb = sb + 32768 + (kt & 1) * 8192;
        const uint32_t* mrow = (const uint32_t*)(sm + 49152 + (kt & 1) * 1024);

        if (kt == 0) {
            #pragma unroll
            for (int kc = 0; kc < 4; kc++)
                ldsm4(qa + kc * 4, sb + SW((m0 + lr + (g & 1) * 8) * 128 + kc * 32 + (g >> 1) * 16));
        }

        float c[8][4] = {};
        #pragma unroll
        for (int nt = 0; nt < 8; nt++) {
            uint32_t bk[8];
            ldsm4(bk,     kb + SW((nt * 8 + lr) * 128 + g * 16));
            ldsm4(bk + 4, kb + SW((nt * 8 + lr) * 128 + g * 16 + 64));
            #pragma unroll
            for (int kc = 0; kc < 4; kc++) mma16816(c[nt], qa + 4 * kc, bk + 2 * kc);
        }

        const uint32_t ml0 = mrow[(m0 + tq) * 2],     mh0 = mrow[(m0 + tq) * 2 + 1];
        const uint32_t ml1 = mrow[(m0 + tq + 8) * 2], mh1 = mrow[(m0 + tq + 8) * 2 + 1];
        uint32_t pa[16];
        #pragma unroll
        for (int nt = 0; nt < 8; nt++) {
            const int sh = ((nt & 3) << 3) + tr * 2;
            const uint32_t w0 = (nt < 4) ? ml0 : mh0;
            const uint32_t w1 = (nt < 4) ? ml1 : mh1;
            float p0 = ex2(((w0 >> sh) & 1u)       ? c[nt][0] * CE : -1e30f);
            float p1 = ex2(((w0 >> (sh + 1)) & 1u) ? c[nt][1] * CE : -1e30f);
            float p2 = ex2(((w1 >> sh) & 1u)       ? c[nt][2] * CE : -1e30f);
            float p3 = ex2(((w1 >> (sh + 1)) & 1u) ? c[nt][3] * CE : -1e30f);
            l0 += p0 + p1;
            l1 += p2 + p3;
            pa[nt * 2]     = packh2(p0, p1);
            pa[nt * 2 + 1] = packh2(p2, p3);
        }

        #pragma unroll
        for (int nt = 0; nt < 8; nt++) {
            uint32_t bv[8];
            ldsm4t(bv,     vb + SW((g * 8 + lr) * 128 + nt * 16));
            ldsm4t(bv + 4, vb + SW((g * 8 + lr + 32) * 128 + nt * 16));
            #pragma unroll
            for (int kc = 0; kc < 4; kc++) mma16816(o[nt], pa + 4 * kc, bv + 2 * kc);
        }
        __syncthreads();
    }

    l0 += __shfl_xor_sync(0xffffffffu, l0, 1);
    l0 += __shfl_xor_sync(0xffffffffu, l0, 2);
    l1 += __shfl_xor_sync(0xffffffffu, l1, 1);
    l1 += __shfl_xor_sync(0xffffffffu, l1, 2);
    const float inv0 = 1.0f / l0, inv1 = 1.0f / l1;

    const int rl = qt * 128 + m0 + tq;
    __half* og = g_att + ((long)b * Sc + rl) * HID + h * 64;
    #pragma unroll
    for (int nt = 0; nt < 8; nt++) {
        const int col = nt * 8 + tr * 2;
        *(__half2*)(og + col)           = __floats2half2_rn(o[nt][0] * inv0, o[nt][1] * inv0);
        *(__half2*)(og + 8 * HID + col) = __floats2half2_rn(o[nt][2] * inv1, o[nt][3] * inv1);
    }
}

// ---------------------------------------------------------------------------
// Kernel 3: out = att @ Wo^T + bo, pure fp16 GEMM, cp.async double-buffered.
// grid (32, 8), 256 threads; CTA tile 128x128, K chunks of 64.
// smem: 2 x (A 16K + B 16K) = 64 KB dynamic.
// ---------------------------------------------------------------------------
constexpr int OP_SMEM = 65536;

__global__ __launch_bounds__(256, 2) void outproj_kernel(
    const float* __restrict__ bo, float* __restrict__ out)
{
    extern __shared__ char sm[];
    const uint32_t sb = smem_u32(sm);
    const int tid = threadIdx.x, lane = tid & 31, w = tid >> 5;
    const int r0 = blockIdx.x * 128, c0 = blockIdx.y * 128;
    const int lr = lane & 7, g = lane >> 3, tq = lane >> 2, tr = lane & 3;
    const int m0 = w * 16;

    auto prefetch = [&](int kt) {
        const uint32_t base = sb + (kt & 1) * 32768;
        const char* ag = (const char*)(g_att + (long)r0 * HID + kt * 64);
        const char* bg = (const char*)(g_wo  + (long)c0 * HID + kt * 64);
        for (int i = tid; i < 1024; i += 256) {
            const int row = i >> 3, q = i & 7;
            const uint32_t off = SW((uint32_t)(row * 128 + q * 16));
            cp16(base + off,         ag + (long)row * (HID * 2) + q * 16);
            cp16(base + 16384 + off, bg + (long)row * (HID * 2) + q * 16);
        }
    };

    prefetch(0);
    cp_commit();

    float c[16][4] = {};

    for (int kt = 0; kt < 16; kt++) {
        if (kt < 15) { prefetch(kt + 1); cp_commit(); cp_wait<1>(); }
        else         { cp_wait<0>(); }
        __syncthreads();

        const uint32_t ab = sb + (kt & 1) * 32768;
        const uint32_t bb = ab + 16384;

        uint32_t aa[16];
        #pragma unroll
        for (int kc = 0; kc < 4; kc++)
            ldsm4(aa + kc * 4, ab + SW((m0 + lr + (g & 1) * 8) * 128 + kc * 32 + (g >> 1) * 16));

        #pragma unroll
        for (int nt = 0; nt < 16; nt++) {
            uint32_t bbr[8];
            ldsm4(bbr,     bb + SW((nt * 8 + lr) * 128 + g * 16));
            ldsm4(bbr + 4, bb + SW((nt * 8 + lr) * 128 + g * 16 + 64));
            #pragma unroll
            for (int kc = 0; kc < 4; kc++) mma16816(c[nt], aa + 4 * kc, bbr + 2 * kc);
        }
        __syncthreads();
    }

    const int rl = r0 + m0 + tq;
    #pragma unroll
    for (int nt = 0; nt < 16; nt++) {
        const int col = c0 + nt * 8 + tr * 2;
        const float b0 = bo[col], b1 = bo[col + 1];
        *(float2*)(out + (long)rl * HID + col)       = make_float2(c[nt][0] + b0, c[nt][1] + b1);
        *(float2*)(out + (long)(rl + 8) * HID + col) = make_float2(c[nt][2] + b0, c[nt][3] + b1);
    }
}

// ---------------------------------------------------------------------------
extern "C" void kernel_launch(void* const* d_in, const int* in_sizes, int n_in,
                              void* d_out, int out_size)
{
    const float* q    = (const float*)d_in[0];
    const float* k    = (const float*)d_in[1];
    const float* v    = (const float*)d_in[2];
    const int*   mask = (const int*)  d_in[3];
    const float* Wq   = (const float*)d_in[4];
    const float* bq   = (const float*)d_in[5];
    const float* Wk   = (const float*)d_in[6];
    const float* bk   = (const float*)d_in[7];
    const float* Wv   = (const float*)d_in[8];
    const float* bv   = (const float*)d_in[9];
    const float* Wo   = (const float*)d_in[10];
    const float* bo   = (const float*)d_in[11];
    float* out = (float*)d_out;

    cudaFuncSetAttribute(attn_kernel, cudaFuncAttributeMaxDynamicSharedMemorySize, ATT_SMEM);
    cudaFuncSetAttribute(outproj_kernel, cudaFuncAttributeMaxDynamicSharedMemorySize, OP_SMEM);

    pack_mask_kernel<<<Bc * Sc * Sc / 256, 256>>>(mask);
    convert_wo_kernel<<<HID * HID / 4 / 256, 256>>>(Wo);
    proj_kernel<<<dim3(512, 3), 256>>>(q, k, v, Wq, bq, Wk, bk, Wv, bv);
    attn_kernel<<<512, 256, ATT_SMEM>>>();
    outproj_kernel<<<dim3(32, 8), 256, OP_SMEM>>>(bo, out);
}

// round 5
// speedup vs baseline: 7.1053x; 1.0668x over previous
#include <cuda_runtime.h>
#include <cuda_fp16.h>
#include <cstdint>

// ---------------- problem constants ----------------
constexpr int Bc = 2;
constexpr int Sc = 2048;
constexpr int Hc = 16;
constexpr int Dc = 64;
constexpr int HID = 1024;
constexpr float CE = 0.03125f * 1.44269504088896340736f;  // (1/sqrt(1024)) * log2(e)

// ---------------- device scratch ----------------
__device__ __half   g_q[Bc * Hc * Sc * Dc];        // [B,H,S,D] fp16 (PRE-SCALED by CE)
__device__ __half   g_k[Bc * Hc * Sc * Dc];        // [B,H,S,D] fp16
__device__ __half   g_v[Bc * Hc * Sc * Dc];        // [B,H,S,D] fp16
__device__ __half   g_att[Bc * Sc * HID];          // [B,S,HID] fp16
__device__ __half   g_wo[HID * HID];               // Wo fp16
__device__ uint32_t g_maskp[Bc * Sc * (Sc / 32)];  // bit-packed mask

// ---------------- helpers ----------------
__device__ __forceinline__ uint32_t smem_u32(const void* p) {
    uint32_t a;
    asm("{ .reg .u64 t; cvta.to.shared.u64 t, %1; cvt.u32.u64 %0, t; }" : "=r"(a) : "l"(p));
    return a;
}
__device__ __forceinline__ uint32_t SW(uint32_t x) { return x ^ ((x >> 3) & 0x70); }

__device__ __forceinline__ void ldsm4(uint32_t* r, uint32_t a) {
    asm volatile("ldmatrix.sync.aligned.m8n8.x4.shared.b16 {%0,%1,%2,%3}, [%4];"
                 : "=r"(r[0]), "=r"(r[1]), "=r"(r[2]), "=r"(r[3]) : "r"(a));
}
__device__ __forceinline__ void ldsm4t(uint32_t* r, uint32_t a) {
    asm volatile("ldmatrix.sync.aligned.m8n8.x4.trans.shared.b16 {%0,%1,%2,%3}, [%4];"
                 : "=r"(r[0]), "=r"(r[1]), "=r"(r[2]), "=r"(r[3]) : "r"(a));
}
__device__ __forceinline__ void mma16816(float* c, const uint32_t* a, const uint32_t* b) {
    asm volatile("mma.sync.aligned.m16n8k16.row.col.f32.f16.f16.f32 "
                 "{%0,%1,%2,%3}, {%4,%5,%6,%7}, {%8,%9}, {%0,%1,%2,%3};"
                 : "+f"(c[0]), "+f"(c[1]), "+f"(c[2]), "+f"(c[3])
                 : "r"(a[0]), "r"(a[1]), "r"(a[2]), "r"(a[3]), "r"(b[0]), "r"(b[1]));
}
__device__ __forceinline__ void cp16(uint32_t d, const void* s) {
    asm volatile("cp.async.cg.shared.global [%0], [%1], 16;" :: "r"(d), "l"(s) : "memory");
}
__device__ __forceinline__ void cp8(uint32_t d, const void* s) {
    asm volatile("cp.async.ca.shared.global [%0], [%1], 8;" :: "r"(d), "l"(s) : "memory");
}
__device__ __forceinline__ void cp_commit() {
    asm volatile("cp.async.commit_group;" ::: "memory");
}
template <int N> __device__ __forceinline__ void cp_wait() {
    asm volatile("cp.async.wait_group %0;" :: "n"(N) : "memory");
}
// packed half2 exp2
__device__ __forceinline__ uint32_t ex2_h2(uint32_t x) {
    uint32_t r;
    asm("ex2.approx.f16x2 %0, %1;" : "=r"(r) : "r"(x));
    return r;
}
__device__ __forceinline__ uint32_t pack_h2(float a, float b) {
    __half2 h = __floats2half2_rn(a, b);   // a -> low half
    return *reinterpret_cast<uint32_t*>(&h);
}
__device__ __forceinline__ uint32_t hadd2u(uint32_t a, uint32_t b) {
    uint32_t r;
    asm("add.f16x2 %0, %1, %2;" : "=r"(r) : "r"(a), "r"(b));
    return r;
}

// ---------------------------------------------------------------------------
// Kernel 0a: bit-pack the mask
// ---------------------------------------------------------------------------
__global__ __launch_bounds__(256) void pack_mask_kernel(const int* __restrict__ mask) {
    long i = (long)blockIdx.x * 256 + threadIdx.x;
    int v = mask[i];
    uint32_t bal = __ballot_sync(0xffffffffu, v != 0);
    if ((threadIdx.x & 31) == 0) g_maskp[i >> 5] = bal;
}

// ---------------------------------------------------------------------------
// Kernel 0b: convert Wo to fp16 once
// ---------------------------------------------------------------------------
__global__ __launch_bounds__(256) void convert_wo_kernel(const float* __restrict__ Wo) {
    long i = (long)blockIdx.x * 256 + threadIdx.x;
    float4 f = ((const float4*)Wo)[i];
    ((__half2*)g_wo)[i * 2]     = __floats2half2_rn(f.x, f.y);
    ((__half2*)g_wo)[i * 2 + 1] = __floats2half2_rn(f.z, f.w);
}

// ---------------------------------------------------------------------------
// Kernel 1: fused QKV projection with mma.sync (fp16 in, fp32 accum).
// Q output is PRE-SCALED by CE so attention scores are direct exp2 arguments.
// ---------------------------------------------------------------------------
__global__ __launch_bounds__(256) void proj_kernel(
    const float* __restrict__ xq, const float* __restrict__ xk, const float* __restrict__ xv,
    const float* __restrict__ Wq, const float* __restrict__ bq,
    const float* __restrict__ Wk, const float* __restrict__ bk,
    const float* __restrict__ Wv, const float* __restrict__ bv)
{
    __shared__ __half Xs[128 * 64];
    __shared__ __half Ws[64 * 64];
    __shared__ float  bs[64];

    const int which = blockIdx.y;
    const float* X    = (which == 0) ? xq : (which == 1) ? xk : xv;
    const float* Wt   = (which == 0) ? Wq : (which == 1) ? Wk : Wv;
    const float* bias = (which == 0) ? bq : (which == 1) ? bk : bv;
    __half* outp      = (which == 0) ? g_q : (which == 1) ? g_k : g_v;
    const float oscale = (which == 0) ? CE : 1.0f;

    const int tid = threadIdx.x, lane = tid & 31, w = tid >> 5;
    const long R0 = (long)blockIdx.x * 128;

    const uint32_t xb = smem_u32(Xs), wb = smem_u32(Ws);
    const float4* Xg = (const float4*)(X + R0 * 64);
    for (int i = tid; i < 2048; i += 256) {
        float4 f = Xg[i];
        uint32_t off = SW((uint32_t)i * 8);
        *(__half2*)((char*)Xs + off)     = __floats2half2_rn(f.x, f.y);
        *(__half2*)((char*)Xs + off + 4) = __floats2half2_rn(f.z, f.w);
    }
    const float4* Wg = (const float4*)Wt;
    for (int i = tid; i < 1024; i += 256) {
        float4 f = Wg[i];
        uint32_t off = SW((uint32_t)i * 8);
        *(__half2*)((char*)Ws + off)     = __floats2half2_rn(f.x, f.y);
        *(__half2*)((char*)Ws + off + 4) = __floats2half2_rn(f.z, f.w);
    }
    if (tid < 64) bs[tid] = bias[tid];
    __syncthreads();

    const int lr = lane & 7, g = lane >> 3, tq = lane >> 2, tr = lane & 3;
    const int m0 = w * 16;

    uint32_t qa[16];
    #pragma unroll
    for (int kc = 0; kc < 4; kc++)
        ldsm4(qa + kc * 4, xb + SW((m0 + lr + (g & 1) * 8) * 128 + kc * 32 + (g >> 1) * 16));

    float c[8][4] = {};
    #pragma unroll
    for (int nt = 0; nt < 8; nt++) {
        uint32_t bk[8];
        ldsm4(bk,     wb + SW((nt * 8 + lr) * 128 + g * 16));
        ldsm4(bk + 4, wb + SW((nt * 8 + lr) * 128 + g * 16 + 64));
        #pragma unroll
        for (int kc = 0; kc < 4; kc++) mma16816(c[nt], qa + 4 * kc, bk + 2 * kc);
    }

    const long Rw = R0 + m0;
    const int b = (int)(Rw >> 15);
    const int s = (int)((Rw >> 4) & 2047);
    #pragma unroll
    for (int nt = 0; nt < 8; nt++) {
        const int col = nt * 8 + tr * 2;
        const float b0 = bs[col], b1 = bs[col + 1];
        const int hl = tq, hh = tq + 8;
        __half2* lo = (__half2*)(outp + (((long)(b * Hc + hl) * Sc + s) * Dc) + col);
        __half2* hi = (__half2*)(outp + (((long)(b * Hc + hh) * Sc + s) * Dc) + col);
        *lo = __floats2half2_rn((c[nt][0] + b0) * oscale, (c[nt][1] + b1) * oscale);
        *hi = __floats2half2_rn((c[nt][2] + b0) * oscale, (c[nt][3] + b1) * oscale);
    }
}

// ---------------------------------------------------------------------------
// Kernel 2: flash attention with mma.sync; f16x2 exp softmax.
// ---------------------------------------------------------------------------
constexpr int ATT_SMEM = 51200;

__global__ __launch_bounds__(256, 2) void attn_kernel()
{
    extern __shared__ char sm[];
    const uint32_t sb = smem_u32(sm);
    const int tid = threadIdx.x, lane = tid & 31, w = tid >> 5;
    const int bh = blockIdx.x >> 4, qt = blockIdx.x & 15;
    const int b = bh >> 4, h = bh & 15;

    const __half* Qg = g_q + ((long)bh * Sc + qt * 128) * Dc;
    const __half* Kg = g_k + (long)bh * Sc * Dc;
    const __half* Vg = g_v + (long)bh * Sc * Dc;
    const uint32_t* Mp = g_maskp + ((long)b * Sc + qt * 128) * (Sc / 32);

    for (int i = tid; i < 1024; i += 256)
        cp16(sb + (((uint32_t)i * 16) & ~1023u) + SW(((uint32_t)i * 16) & 1023u),
             (const char*)Qg + (long)i * 16);

    auto prefetch = [&](int kt) {
        const int bo = kt & 1;
        const uint32_t kb = sb + 16384 + bo * 8192;
        const uint32_t vb = sb + 32768 + bo * 8192;
        const char* kg = (const char*)(Kg + (long)kt * 64 * 64);
        const char* vg = (const char*)(Vg + (long)kt * 64 * 64);
        for (int i = tid; i < 512; i += 256) {
            uint32_t off = (((uint32_t)i * 16) & ~1023u) + SW(((uint32_t)i * 16) & 1023u);
            cp16(kb + off, kg + (long)i * 16);
            cp16(vb + off, vg + (long)i * 16);
        }
        const uint32_t mb = sb + 49152 + bo * 1024;
        if (tid < 128)
            cp8(mb + tid * 8, (const void*)(Mp + (long)tid * 64 + kt * 2));
    };

    prefetch(0);
    cp_commit();

    const int lr = lane & 7, g = lane >> 3, tq = lane >> 2, tr = lane & 3;
    const int m0 = w * 16;

    uint32_t qa[16];
    float o[8][4] = {};
    float l0 = 0.0f, l1 = 0.0f;

    for (int kt = 0; kt < 32; kt++) {
        if (kt < 31) { prefetch(kt + 1); cp_commit(); cp_wait<1>(); }
        else         { cp_wait<0>(); }
        __syncthreads();

        const uint32_t kb = sb + 16384 + (kt & 1) * 8192;
        const uint32_t vb = sb + 32768 + (kt & 1) * 8192;
        const uint32_t* mrow = (const uint32_t*)(sm + 49152 + (kt & 1) * 1024);

        if (kt == 0) {
            #pragma unroll
            for (int kc = 0; kc < 4; kc++)
                ldsm4(qa + kc * 4, sb + SW((m0 + lr + (g & 1) * 8) * 128 + kc * 32 + (g >> 1) * 16));
        }

        // scores (already exp2 arguments; Q was pre-scaled by CE)
        float c[8][4] = {};
        #pragma unroll
        for (int nt = 0; nt < 8; nt++) {
            uint32_t bk[8];
            ldsm4(bk,     kb + SW((nt * 8 + lr) * 128 + g * 16));
            ldsm4(bk + 4, kb + SW((nt * 8 + lr) * 128 + g * 16 + 64));
            #pragma unroll
            for (int kc = 0; kc < 4; kc++) mma16816(c[nt], qa + 4 * kc, bk + 2 * kc);
        }

        // mask + f16x2 exp; P stays packed as A-fragments; l via HADD2
        const uint32_t wa_lo = mrow[(m0 + tq) * 2]     >> (tr * 2);
        const uint32_t wa_hi = mrow[(m0 + tq) * 2 + 1] >> (tr * 2);
        const uint32_t wb_lo = mrow[(m0 + tq + 8) * 2]     >> (tr * 2);
        const uint32_t wb_hi = mrow[(m0 + tq + 8) * 2 + 1] >> (tr * 2);

        uint32_t pa[16];
        uint32_t lacc0 = 0, lacc1 = 0;   // half2 zero
        #pragma unroll
        for (int nt = 0; nt < 8; nt++) {
            const int sh = (nt & 3) << 3;
            const uint32_t wa = (nt < 4) ? wa_lo : wa_hi;
            const uint32_t wb = (nt < 4) ? wb_lo : wb_hi;
            float s0 = ((wa >> sh) & 1u)       ? c[nt][0] : -1e30f;
            float s1 = ((wa >> (sh + 1)) & 1u) ? c[nt][1] : -1e30f;
            float s2 = ((wb >> sh) & 1u)       ? c[nt][2] : -1e30f;
            float s3 = ((wb >> (sh + 1)) & 1u) ? c[nt][3] : -1e30f;
            uint32_t p01 = ex2_h2(pack_h2(s0, s1));
            uint32_t p23 = ex2_h2(pack_h2(s2, s3));
            pa[nt * 2]     = p01;
            pa[nt * 2 + 1] = p23;
            lacc0 = hadd2u(lacc0, p01);
            lacc1 = hadd2u(lacc1, p23);
        }
        {
            float2 f0 = __half22float2(*reinterpret_cast<__half2*>(&lacc0));
            float2 f1 = __half22float2(*reinterpret_cast<__half2*>(&lacc1));
            l0 += f0.x + f0.y;
            l1 += f1.x + f1.y;
        }

        // O += P @ V
        #pragma unroll
        for (int nt = 0; nt < 8; nt++) {
            uint32_t bv[8];
            ldsm4t(bv,     vb + SW((g * 8 + lr) * 128 + nt * 16));
            ldsm4t(bv + 4, vb + SW((g * 8 + lr + 32) * 128 + nt * 16));
            #pragma unroll
            for (int kc = 0; kc < 4; kc++) mma16816(o[nt], pa + 4 * kc, bv + 2 * kc);
        }
        __syncthreads();
    }

    l0 += __shfl_xor_sync(0xffffffffu, l0, 1);
    l0 += __shfl_xor_sync(0xffffffffu, l0, 2);
    l1 += __shfl_xor_sync(0xffffffffu, l1, 1);
    l1 += __shfl_xor_sync(0xffffffffu, l1, 2);
    const float inv0 = 1.0f / l0, inv1 = 1.0f / l1;

    const int rl = qt * 128 + m0 + tq;
    __half* og = g_att + ((long)b * Sc + rl) * HID + h * 64;
    #pragma unroll
    for (int nt = 0; nt < 8; nt++) {
        const int col = nt * 8 + tr * 2;
        *(__half2*)(og + col)           = __floats2half2_rn(o[nt][0] * inv0, o[nt][1] * inv0);
        *(__half2*)(og + 8 * HID + col) = __floats2half2_rn(o[nt][2] * inv1, o[nt][3] * inv1);
    }
}

// ---------------------------------------------------------------------------
// Kernel 3: out = att @ Wo^T + bo, pure fp16 GEMM, cp.async double-buffered.
// ---------------------------------------------------------------------------
constexpr int OP_SMEM = 65536;

__global__ __launch_bounds__(256, 2) void outproj_kernel(
    const float* __restrict__ bo, float* __restrict__ out)
{
    extern __shared__ char sm[];
    const uint32_t sb = smem_u32(sm);
    const int tid = threadIdx.x, lane = tid & 31, w = tid >> 5;
    const int r0 = blockIdx.x * 128, c0 = blockIdx.y * 128;
    const int lr = lane & 7, g = lane >> 3, tq = lane >> 2, tr = lane & 3;
    const int m0 = w * 16;

    auto prefetch = [&](int kt) {
        const uint32_t base = sb + (kt & 1) * 32768;
        const char* ag = (const char*)(g_att + (long)r0 * HID + kt * 64);
        const char* bg = (const char*)(g_wo  + (long)c0 * HID + kt * 64);
        for (int i = tid; i < 1024; i += 256) {
            const int row = i >> 3, q = i & 7;
            const uint32_t off = SW((uint32_t)(row * 128 + q * 16));
            cp16(base + off,         ag + (long)row * (HID * 2) + q * 16);
            cp16(base + 16384 + off, bg + (long)row * (HID * 2) + q * 16);
        }
    };

    prefetch(0);
    cp_commit();

    float c[16][4] = {};

    for (int kt = 0; kt < 16; kt++) {
        if (kt < 15) { prefetch(kt + 1); cp_commit(); cp_wait<1>(); }
        else         { cp_wait<0>(); }
        __syncthreads();

        const uint32_t ab = sb + (kt & 1) * 32768;
        const uint32_t bb = ab + 16384;

        uint32_t aa[16];
        #pragma unroll
        for (int kc = 0; kc < 4; kc++)
            ldsm4(aa + kc * 4, ab + SW((m0 + lr + (g & 1) * 8) * 128 + kc * 32 + (g >> 1) * 16));

        #pragma unroll
        for (int nt = 0; nt < 16; nt++) {
            uint32_t bbr[8];
            ldsm4(bbr,     bb + SW((nt * 8 + lr) * 128 + g * 16));
            ldsm4(bbr + 4, bb + SW((nt * 8 + lr) * 128 + g * 16 + 64));
            #pragma unroll
            for (int kc = 0; kc < 4; kc++) mma16816(c[nt], aa + 4 * kc, bbr + 2 * kc);
        }
        __syncthreads();
    }

    const int rl = r0 + m0 + tq;
    #pragma unroll
    for (int nt = 0; nt < 16; nt++) {
        const int col = c0 + nt * 8 + tr * 2;
        const float b0 = bo[col], b1 = bo[col + 1];
        *(float2*)(out + (long)rl * HID + col)       = make_float2(c[nt][0] + b0, c[nt][1] + b1);
        *(float2*)(out + (long)(rl + 8) * HID + col) = make_float2(c[nt][2] + b0, c[nt][3] + b1);
    }
}

// ---------------------------------------------------------------------------
extern "C" void kernel_launch(void* const* d_in, const int* in_sizes, int n_in,
                              void* d_out, int out_size)
{
    const float* q    = (const float*)d_in[0];
    const float* k    = (const float*)d_in[1];
    const float* v    = (const float*)d_in[2];
    const int*   mask = (const int*)  d_in[3];
    const float* Wq   = (const float*)d_in[4];
    const float* bq   = (const float*)d_in[5];
    const float* Wk   = (const float*)d_in[6];
    const float* bk   = (const float*)d_in[7];
    const float* Wv   = (const float*)d_in[8];
    const float* bv   = (const float*)d_in[9];
    const float* Wo   = (const float*)d_in[10];
    const float* bo   = (const float*)d_in[11];
    float* out = (float*)d_out;

    cudaFuncSetAttribute(attn_kernel, cudaFuncAttributeMaxDynamicSharedMemorySize, ATT_SMEM);
    cudaFuncSetAttribute(outproj_kernel, cudaFuncAttributeMaxDynamicSharedMemorySize, OP_SMEM);

    pack_mask_kernel<<<Bc * Sc * Sc / 256, 256>>>(mask);
    convert_wo_kernel<<<HID * HID / 4 / 256, 256>>>(Wo);
    proj_kernel<<<dim3(512, 3), 256>>>(q, k, v, Wq, bq, Wk, bk, Wv, bv);
    attn_kernel<<<512, 256, ATT_SMEM>>>();
    outproj_kernel<<<dim3(32, 8), 256, OP_SMEM>>>(bo, out);
}

// round 6
// speedup vs baseline: 7.6091x; 1.0709x over previous
#include <cuda_runtime.h>
#include <cuda_fp16.h>
#include <cstdint>

// ---------------- problem constants ----------------
constexpr int Bc = 2;
constexpr int Sc = 2048;
constexpr int Hc = 16;
constexpr int Dc = 64;
constexpr int HID = 1024;
constexpr float CE = 0.03125f * 1.44269504088896340736f;  // (1/sqrt(1024)) * log2(e)

// ---------------- device scratch ----------------
__device__ __half   g_q[Bc * Hc * Sc * Dc];        // [B,H,S,D] fp16 (PRE-SCALED by CE)
__device__ __half   g_k[Bc * Hc * Sc * Dc];        // [B,H,S,D] fp16
__device__ __half   g_v[Bc * Hc * Sc * Dc];        // [B,H,S,D] fp16
__device__ __half   g_att[Bc * Sc * HID];          // [B,S,HID] fp16
__device__ __half   g_wo[HID * HID];               // Wo fp16
__device__ uint32_t g_maskp[Bc * Sc * (Sc / 32)];  // bit-packed mask

// ---------------- helpers ----------------
__device__ __forceinline__ uint32_t smem_u32(const void* p) {
    uint32_t a;
    asm("{ .reg .u64 t; cvta.to.shared.u64 t, %1; cvt.u32.u64 %0, t; }" : "=r"(a) : "l"(p));
    return a;
}
__device__ __forceinline__ uint32_t SW(uint32_t x) { return x ^ ((x >> 3) & 0x70); }

__device__ __forceinline__ void ldsm4(uint32_t* r, uint32_t a) {
    asm volatile("ldmatrix.sync.aligned.m8n8.x4.shared.b16 {%0,%1,%2,%3}, [%4];"
                 : "=r"(r[0]), "=r"(r[1]), "=r"(r[2]), "=r"(r[3]) : "r"(a));
}
__device__ __forceinline__ void ldsm4t(uint32_t* r, uint32_t a) {
    asm volatile("ldmatrix.sync.aligned.m8n8.x4.trans.shared.b16 {%0,%1,%2,%3}, [%4];"
                 : "=r"(r[0]), "=r"(r[1]), "=r"(r[2]), "=r"(r[3]) : "r"(a));
}
__device__ __forceinline__ void mma16816(float* c, const uint32_t* a, const uint32_t* b) {
    asm volatile("mma.sync.aligned.m16n8k16.row.col.f32.f16.f16.f32 "
                 "{%0,%1,%2,%3}, {%4,%5,%6,%7}, {%8,%9}, {%0,%1,%2,%3};"
                 : "+f"(c[0]), "+f"(c[1]), "+f"(c[2]), "+f"(c[3])
                 : "r"(a[0]), "r"(a[1]), "r"(a[2]), "r"(a[3]), "r"(b[0]), "r"(b[1]));
}
__device__ __forceinline__ void cp16(uint32_t d, const void* s) {
    asm volatile("cp.async.cg.shared.global [%0], [%1], 16;" :: "r"(d), "l"(s) : "memory");
}
__device__ __forceinline__ void cp8(uint32_t d, const void* s) {
    asm volatile("cp.async.ca.shared.global [%0], [%1], 8;" :: "r"(d), "l"(s) : "memory");
}
__device__ __forceinline__ void cp_commit() {
    asm volatile("cp.async.commit_group;" ::: "memory");
}
template <int N> __device__ __forceinline__ void cp_wait() {
    asm volatile("cp.async.wait_group %0;" :: "n"(N) : "memory");
}
__device__ __forceinline__ uint32_t ex2_h2(uint32_t x) {
    uint32_t r;
    asm("ex2.approx.f16x2 %0, %1;" : "=r"(r) : "r"(x));
    return r;
}
__device__ __forceinline__ uint32_t pack_h2(float a, float b) {
    __half2 h = __floats2half2_rn(a, b);
    return *reinterpret_cast<uint32_t*>(&h);
}
__device__ __forceinline__ uint32_t hadd2u(uint32_t a, uint32_t b) {
    uint32_t r;
    asm("add.f16x2 %0, %1, %2;" : "=r"(r) : "r"(a), "r"(b));
    return r;
}

// ---------------------------------------------------------------------------
// Kernel 0a: bit-pack the mask
// ---------------------------------------------------------------------------
__global__ __launch_bounds__(256) void pack_mask_kernel(const int* __restrict__ mask) {
    long i = (long)blockIdx.x * 256 + threadIdx.x;
    int v = mask[i];
    uint32_t bal = __ballot_sync(0xffffffffu, v != 0);
    if ((threadIdx.x & 31) == 0) g_maskp[i >> 5] = bal;
}

// ---------------------------------------------------------------------------
// Kernel 0b: convert Wo to fp16 once
// ---------------------------------------------------------------------------
__global__ __launch_bounds__(256) void convert_wo_kernel(const float* __restrict__ Wo) {
    long i = (long)blockIdx.x * 256 + threadIdx.x;
    float4 f = ((const float4*)Wo)[i];
    ((__half2*)g_wo)[i * 2]     = __floats2half2_rn(f.x, f.y);
    ((__half2*)g_wo)[i * 2 + 1] = __floats2half2_rn(f.z, f.w);
}

// ---------------------------------------------------------------------------
// Kernel 1: fused QKV projection with mma.sync (fp16 in, fp32 accum).
// Q output is PRE-SCALED by CE.
// ---------------------------------------------------------------------------
__global__ __launch_bounds__(256) void proj_kernel(
    const float* __restrict__ xq, const float* __restrict__ xk, const float* __restrict__ xv,
    const float* __restrict__ Wq, const float* __restrict__ bq,
    const float* __restrict__ Wk, const float* __restrict__ bk,
    const float* __restrict__ Wv, const float* __restrict__ bv)
{
    __shared__ __half Xs[128 * 64];
    __shared__ __half Ws[64 * 64];
    __shared__ float  bs[64];

    const int which = blockIdx.y;
    const float* X    = (which == 0) ? xq : (which == 1) ? xk : xv;
    const float* Wt   = (which == 0) ? Wq : (which == 1) ? Wk : Wv;
    const float* bias = (which == 0) ? bq : (which == 1) ? bk : bv;
    __half* outp      = (which == 0) ? g_q : (which == 1) ? g_k : g_v;
    const float oscale = (which == 0) ? CE : 1.0f;

    const int tid = threadIdx.x, lane = tid & 31, w = tid >> 5;
    const long R0 = (long)blockIdx.x * 128;

    const uint32_t xb = smem_u32(Xs), wb = smem_u32(Ws);
    const float4* Xg = (const float4*)(X + R0 * 64);
    for (int i = tid; i < 2048; i += 256) {
        float4 f = Xg[i];
        uint32_t off = SW((uint32_t)i * 8);
        *(__half2*)((char*)Xs + off)     = __floats2half2_rn(f.x, f.y);
        *(__half2*)((char*)Xs + off + 4) = __floats2half2_rn(f.z, f.w);
    }
    const float4* Wg = (const float4*)Wt;
    for (int i = tid; i < 1024; i += 256) {
        float4 f = Wg[i];
        uint32_t off = SW((uint32_t)i * 8);
        *(__half2*)((char*)Ws + off)     = __floats2half2_rn(f.x, f.y);
        *(__half2*)((char*)Ws + off + 4) = __floats2half2_rn(f.z, f.w);
    }
    if (tid < 64) bs[tid] = bias[tid];
    __syncthreads();

    const int lr = lane & 7, g = lane >> 3, tq = lane >> 2, tr = lane & 3;
    const int m0 = w * 16;

    uint32_t qa[16];
    #pragma unroll
    for (int kc = 0; kc < 4; kc++)
        ldsm4(qa + kc * 4, xb + SW((m0 + lr + (g & 1) * 8) * 128 + kc * 32 + (g >> 1) * 16));

    float c[8][4] = {};
    #pragma unroll
    for (int nt = 0; nt < 8; nt++) {
        uint32_t bk[8];
        ldsm4(bk,     wb + SW((nt * 8 + lr) * 128 + g * 16));
        ldsm4(bk + 4, wb + SW((nt * 8 + lr) * 128 + g * 16 + 64));
        #pragma unroll
        for (int kc = 0; kc < 4; kc++) mma16816(c[nt], qa + 4 * kc, bk + 2 * kc);
    }

    const long Rw = R0 + m0;
    const int b = (int)(Rw >> 15);
    const int s = (int)((Rw >> 4) & 2047);
    #pragma unroll
    for (int nt = 0; nt < 8; nt++) {
        const int col = nt * 8 + tr * 2;
        const float b0 = bs[col], b1 = bs[col + 1];
        const int hl = tq, hh = tq + 8;
        __half2* lo = (__half2*)(outp + (((long)(b * Hc + hl) * Sc + s) * Dc) + col);
        __half2* hi = (__half2*)(outp + (((long)(b * Hc + hh) * Sc + s) * Dc) + col);
        *lo = __floats2half2_rn((c[nt][0] + b0) * oscale, (c[nt][1] + b1) * oscale);
        *hi = __floats2half2_rn((c[nt][2] + b0) * oscale, (c[nt][3] + b1) * oscale);
    }
}

// ---------------------------------------------------------------------------
// Kernel 2: flash attention. 128-thr CTAs (4 warps x 16 q-rows, q-tile 64),
// 3-stage cp.async ring, ONE __syncthreads per k-tile. Mask ring reuses the
// dead Q staging area. 4 CTAs/SM.
// smem: Q/mask 8K | K ring 3x8K | V ring 3x8K = 57344 B
// ---------------------------------------------------------------------------
constexpr int ATT_SMEM = 57344;

__global__ __launch_bounds__(128, 4) void attn_kernel()
{
    extern __shared__ char sm[];
    const uint32_t sb = smem_u32(sm);
    const int tid = threadIdx.x, lane = tid & 31, w = tid >> 5;
    const int bh = blockIdx.x >> 5, qt = blockIdx.x & 31;
    const int b = bh >> 4, h = bh & 15;

    const __half* Qg = g_q + ((long)bh * Sc + qt * 64) * Dc;
    const __half* Kg = g_k + (long)bh * Sc * Dc;
    const __half* Vg = g_v + (long)bh * Sc * Dc;
    const uint32_t* Mp = g_maskp + ((long)b * Sc + qt * 64) * (Sc / 32);

    // ---- prologue: Q tile (64 rows x 128B) into [0, 8192) ----
    for (int i = tid; i < 512; i += 128)
        cp16(sb + (((uint32_t)i * 16) & ~1023u) + SW(((uint32_t)i * 16) & 1023u),
             (const char*)Qg + (long)i * 16);
    cp_commit();
    cp_wait<0>();
    __syncthreads();

    const int lr = lane & 7, g = lane >> 3, tq = lane >> 2, tr = lane & 3;
    const int m0 = w * 16;

    uint32_t qa[16];
    #pragma unroll
    for (int kc = 0; kc < 4; kc++)
        ldsm4(qa + kc * 4, sb + SW((m0 + lr + (g & 1) * 8) * 128 + kc * 32 + (g >> 1) * 16));
    __syncthreads();   // Q area now dead -> becomes mask ring

    auto prefetch = [&](int kt, int slot) {
        const uint32_t kb = sb + 8192  + slot * 8192;
        const uint32_t vb = sb + 32768 + slot * 8192;
        const char* kg = (const char*)(Kg + (long)kt * 64 * 64);
        const char* vg = (const char*)(Vg + (long)kt * 64 * 64);
        for (int i = tid; i < 512; i += 128) {
            uint32_t off = (((uint32_t)i * 16) & ~1023u) + SW(((uint32_t)i * 16) & 1023u);
            cp16(kb + off, kg + (long)i * 16);
            cp16(vb + off, vg + (long)i * 16);
        }
        if (tid < 64)
            cp8(sb + slot * 512 + tid * 8, (const void*)(Mp + (long)tid * 64 + kt * 2));
    };

    prefetch(0, 0); cp_commit();
    prefetch(1, 1); cp_commit();

    float o[8][4] = {};
    float l0 = 0.0f, l1 = 0.0f;
    int ks = 0, ps = 2;

    for (int kt = 0; kt < 32; kt++) {
        cp_wait<1>();
        __syncthreads();   // slot ks ready for all; slot ps free for rewrite

        if (kt < 30) prefetch(kt + 2, ps);
        cp_commit();

        const uint32_t kb = sb + 8192  + ks * 8192;
        const uint32_t vb = sb + 32768 + ks * 8192;
        const uint32_t* mrow = (const uint32_t*)(sm + ks * 512);

        // scores (exp2 arguments; Q pre-scaled)
        float c[8][4] = {};
        #pragma unroll
        for (int nt = 0; nt < 8; nt++) {
            uint32_t bk[8];
            ldsm4(bk,     kb + SW((nt * 8 + lr) * 128 + g * 16));
            ldsm4(bk + 4, kb + SW((nt * 8 + lr) * 128 + g * 16 + 64));
            #pragma unroll
            for (int kc = 0; kc < 4; kc++) mma16816(c[nt], qa + 4 * kc, bk + 2 * kc);
        }

        // mask + f16x2 exp; l via HADD2
        const uint32_t wa_lo = mrow[(m0 + tq) * 2]     >> (tr * 2);
        const uint32_t wa_hi = mrow[(m0 + tq) * 2 + 1] >> (tr * 2);
        const uint32_t wb_lo = mrow[(m0 + tq + 8) * 2]     >> (tr * 2);
        const uint32_t wb_hi = mrow[(m0 + tq + 8) * 2 + 1] >> (tr * 2);

        uint32_t pa[16];
        uint32_t lacc0 = 0, lacc1 = 0;
        #pragma unroll
        for (int nt = 0; nt < 8; nt++) {
            const int sh = (nt & 3) << 3;
            const uint32_t wa = (nt < 4) ? wa_lo : wa_hi;
            const uint32_t wb = (nt < 4) ? wb_lo : wb_hi;
            float s0 = ((wa >> sh) & 1u)       ? c[nt][0] : -1e30f;
            float s1 = ((wa >> (sh + 1)) & 1u) ? c[nt][1] : -1e30f;
            float s2 = ((wb >> sh) & 1u)       ? c[nt][2] : -1e30f;
            float s3 = ((wb >> (sh + 1)) & 1u) ? c[nt][3] : -1e30f;
            uint32_t p01 = ex2_h2(pack_h2(s0, s1));
            uint32_t p23 = ex2_h2(pack_h2(s2, s3));
            pa[nt * 2]     = p01;
            pa[nt * 2 + 1] = p23;
            lacc0 = hadd2u(lacc0, p01);
            lacc1 = hadd2u(lacc1, p23);
        }
        {
            float2 f0 = __half22float2(*reinterpret_cast<__half2*>(&lacc0));
            float2 f1 = __half22float2(*reinterpret_cast<__half2*>(&lacc1));
            l0 += f0.x + f0.y;
            l1 += f1.x + f1.y;
        }

        // O += P @ V
        #pragma unroll
        for (int nt = 0; nt < 8; nt++) {
            uint32_t bv[8];
            ldsm4t(bv,     vb + SW((g * 8 + lr) * 128 + nt * 16));
            ldsm4t(bv + 4, vb + SW((g * 8 + lr + 32) * 128 + nt * 16));
            #pragma unroll
            for (int kc = 0; kc < 4; kc++) mma16816(o[nt], pa + 4 * kc, bv + 2 * kc);
        }

        if (++ks == 3) ks = 0;
        if (++ps == 3) ps = 0;
    }

    l0 += __shfl_xor_sync(0xffffffffu, l0, 1);
    l0 += __shfl_xor_sync(0xffffffffu, l0, 2);
    l1 += __shfl_xor_sync(0xffffffffu, l1, 1);
    l1 += __shfl_xor_sync(0xffffffffu, l1, 2);
    const float inv0 = 1.0f / l0, inv1 = 1.0f / l1;

    const int rl = qt * 64 + m0 + tq;
    __half* og = g_att + ((long)b * Sc + rl) * HID + h * 64;
    #pragma unroll
    for (int nt = 0; nt < 8; nt++) {
        const int col = nt * 8 + tr * 2;
        *(__half2*)(og + col)           = __floats2half2_rn(o[nt][0] * inv0, o[nt][1] * inv0);
        *(__half2*)(og + 8 * HID + col) = __floats2half2_rn(o[nt][2] * inv1, o[nt][3] * inv1);
    }
}

// ---------------------------------------------------------------------------
// Kernel 3: out = att @ Wo^T + bo, pure fp16 GEMM, cp.async double-buffered.
// ---------------------------------------------------------------------------
constexpr int OP_SMEM = 65536;

__global__ __launch_bounds__(256, 2) void outproj_kernel(
    const float* __restrict__ bo, float* __restrict__ out)
{
    extern __shared__ char sm[];
    const uint32_t sb = smem_u32(sm);
    const int tid = threadIdx.x, lane = tid & 31, w = tid >> 5;
    const int r0 = blockIdx.x * 128, c0 = blockIdx.y * 128;
    const int lr = lane & 7, g = lane >> 3, tq = lane >> 2, tr = lane & 3;
    const int m0 = w * 16;

    auto prefetch = [&](int kt) {
        const uint32_t base = sb + (kt & 1) * 32768;
        const char* ag = (const char*)(g_att + (long)r0 * HID + kt * 64);
        const char* bg = (const char*)(g_wo  + (long)c0 * HID + kt * 64);
        for (int i = tid; i < 1024; i += 256) {
            const int row = i >> 3, q = i & 7;
            const uint32_t off = SW((uint32_t)(row * 128 + q * 16));
            cp16(base + off,         ag + (long)row * (HID * 2) + q * 16);
            cp16(base + 16384 + off, bg + (long)row * (HID * 2) + q * 16);
        }
    };

    prefetch(0);
    cp_commit();

    float c[16][4] = {};

    for (int kt = 0; kt < 16; kt++) {
        if (kt < 15) { prefetch(kt + 1); cp_commit(); cp_wait<1>(); }
        else         { cp_wait<0>(); }
        __syncthreads();

        const uint32_t ab = sb + (kt & 1) * 32768;
        const uint32_t bb = ab + 16384;

        uint32_t aa[16];
        #pragma unroll
        for (int kc = 0; kc < 4; kc++)
            ldsm4(aa + kc * 4, ab + SW((m0 + lr + (g & 1) * 8) * 128 + kc * 32 + (g >> 1) * 16));

        #pragma unroll
        for (int nt = 0; nt < 16; nt++) {
            uint32_t bbr[8];
            ldsm4(bbr,     bb + SW((nt * 8 + lr) * 128 + g * 16));
            ldsm4(bbr + 4, bb + SW((nt * 8 + lr) * 128 + g * 16 + 64));
            #pragma unroll
            for (int kc = 0; kc < 4; kc++) mma16816(c[nt], aa + 4 * kc, bbr + 2 * kc);
        }
        __syncthreads();
    }

    const int rl = r0 + m0 + tq;
    #pragma unroll
    for (int nt = 0; nt < 16; nt++) {
        const int col = c0 + nt * 8 + tr * 2;
        const float b0 = bo[col], b1 = bo[col + 1];
        *(float2*)(out + (long)rl * HID + col)       = make_float2(c[nt][0] + b0, c[nt][1] + b1);
        *(float2*)(out + (long)(rl + 8) * HID + col) = make_float2(c[nt][2] + b0, c[nt][3] + b1);
    }
}

// ---------------------------------------------------------------------------
extern "C" void kernel_launch(void* const* d_in, const int* in_sizes, int n_in,
                              void* d_out, int out_size)
{
    const float* q    = (const float*)d_in[0];
    const float* k    = (const float*)d_in[1];
    const float* v    = (const float*)d_in[2];
    const int*   mask = (const int*)  d_in[3];
    const float* Wq   = (const float*)d_in[4];
    const float* bq   = (const float*)d_in[5];
    const float* Wk   = (const float*)d_in[6];
    const float* bk   = (const float*)d_in[7];
    const float* Wv   = (const float*)d_in[8];
    const float* bv   = (const float*)d_in[9];
    const float* Wo   = (const float*)d_in[10];
    const float* bo   = (const float*)d_in[11];
    float* out = (float*)d_out;

    cudaFuncSetAttribute(attn_kernel, cudaFuncAttributeMaxDynamicSharedMemorySize, ATT_SMEM);
    cudaFuncSetAttribute(outproj_kernel, cudaFuncAttributeMaxDynamicSharedMemorySize, OP_SMEM);

    pack_mask_kernel<<<Bc * Sc * Sc / 256, 256>>>(mask);
    convert_wo_kernel<<<HID * HID / 4 / 256, 256>>>(Wo);
    proj_kernel<<<dim3(512, 3), 256>>>(q, k, v, Wq, bq, Wk, bk, Wv, bv);
    attn_kernel<<<1024, 128, ATT_SMEM>>>();
    outproj_kernel<<<dim3(32, 8), 256, OP_SMEM>>>(bo, out);
}